// round 3
// baseline (speedup 1.0000x reference)
#include <cuda_runtime.h>

// ---------------------------------------------------------------------------
// YOLOv3 detection post-process, round 3: single persistent kernel.
// Stages separated by software grid barriers (sense-reversal, spin):
//   1 conf+hist -> 2 cutoff -> 3 gather(+hist reset) -> 4 sort (blk0)
//   -> 5 decode (warp/cand) -> 6 iou bitmask -> 7 serial NMS + output (blk0)
// ---------------------------------------------------------------------------

#define NTOT   340704
#define N13    16224      // 32*3*13*13
#define OFF26  16224
#define OFF52  81120      // N13 + N26
#define CAP    4096
#define NBINS  4096
#define TOPK   512
#define GRID   148
#define BLK    256
#define NTHR   (GRID * BLK)

__device__ unsigned            g_barcnt;    // zero-init; reset at each barrier
__device__ unsigned            g_barsense;  // monotone across launches
__device__ unsigned            g_hist[NBINS];
__device__ int                 g_cutoff;
__device__ unsigned            g_count;
__device__ unsigned long long  g_keys[CAP];
__device__ unsigned long long  g_skeys[TOPK];
__device__ int                 g_Mv;
__device__ float               g_cand[TOPK * 7];
__device__ unsigned            g_mask[TOPK * 16];

__constant__ float c_anchors[3][3][2] = {
    {{116.f, 90.f}, {156.f, 198.f}, {373.f, 326.f}},   // 13x13, stride 32
    {{ 30.f, 61.f}, { 62.f,  45.f}, { 59.f, 119.f}},   // 26x26, stride 16
    {{ 10.f, 13.f}, { 16.f,  30.f}, { 33.f,  23.f}}};  // 52x52, stride 8
__constant__ float c_stride[3] = {32.f, 16.f, 8.f};

struct SharedState {
    union {
        unsigned long long sk[CAP];        // stage 4: 32 KB
        unsigned           mask[TOPK*16];  // stage 7: 32 KB
    } u;
    unsigned sense;
    int      sM, sn;
    unsigned psum[BLK];
    int      s_seg;
    unsigned s_cumafter;
    unsigned keep[16];
};

// Sense-reversal grid barrier. Requires all GRID blocks co-resident
// (grid == 148 <= SM count, trivial occupancy). Counter resets itself;
// sense increases monotonically across graph replays.
__device__ __forceinline__ void grid_bar(SharedState* sh) {
    __syncthreads();
    if (threadIdx.x == 0) {
        unsigned target = ++sh->sense;
        __threadfence();
        if (atomicAdd(&g_barcnt, 1u) == GRID - 1) {
            g_barcnt = 0;
            __threadfence();
            atomicExch(&g_barsense, target);
        } else {
            while (*(volatile unsigned*)&g_barsense != target) __nanosleep(64);
        }
        __threadfence();
    }
    __syncthreads();
}

__device__ __forceinline__ float sigm(float x) {
    return 1.0f / (1.0f + expf(-x));
}

__device__ __forceinline__ void split_t(int t, int& HW, int& t2, int& off) {
    if (t < N13)        { HW = 169;  t2 = t;         off = 0;     }
    else if (t < OFF52) { HW = 676;  t2 = t - OFF26; off = OFF26; }
    else                { HW = 2704; t2 = t - OFF52; off = OFF52; }
}

__device__ __forceinline__ float conf_at(int t, const float* __restrict__ in13,
                                         const float* __restrict__ in26,
                                         const float* __restrict__ in52,
                                         int& HW, int& t2, int& off) {
    split_t(t, HW, t2, off);
    const float* in = (t < N13) ? in13 : (t < OFF52 ? in26 : in52);
    int b = t2 / (3 * HW);
    int r = t2 - b * 3 * HW;
    int a = r / HW;
    int p = r - a * HW;
    return sigm(in[(b * 255 + a * 85 + 4) * HW + p]);
}

// ---------------------------------------------------------------------------
__global__ void __launch_bounds__(BLK) detector_fused(const float* __restrict__ in13,
                                                      const float* __restrict__ in26,
                                                      const float* __restrict__ in52,
                                                      float* __restrict__ out) {
    __shared__ SharedState sh;
    int tid = threadIdx.x;
    int gid = blockIdx.x * BLK + tid;

    if (tid == 0) sh.sense = *(volatile unsigned*)&g_barsense;
    __syncthreads();

    // ---- Stage 1: conf + histogram --------------------------------------
    for (int k = 0; k < 9; k++) {
        int t = gid + k * NTHR;
        if (t >= NTOT) break;
        int HW, t2, off;
        float conf = conf_at(t, in13, in26, in52, HW, t2, off);
        if (conf > 0.5f) {
            unsigned bin = (__float_as_uint(conf) - 0x3F000000u) >> 11;
            if (bin > NBINS - 1) bin = NBINS - 1;
            atomicAdd(&g_hist[bin], 1u);
        }
    }
    grid_bar(&sh);

    // ---- Stage 2: cutoff (block 0) + count reset -------------------------
    if (blockIdx.x == 0) {
        unsigned loc[16];
        unsigned s = 0;
#pragma unroll
        for (int k = 0; k < 16; k++) { loc[k] = g_hist[tid * 16 + k]; s += loc[k]; }
        sh.psum[tid] = s;
        __syncthreads();
        if (tid == 0) {
            unsigned cum = 0; int seg = -1;
            for (int i = 255; i >= 0; --i) {
                if (cum + sh.psum[i] >= TOPK) { seg = i; break; }
                cum += sh.psum[i];
            }
            sh.s_seg = seg; sh.s_cumafter = cum;
            if (seg < 0) g_cutoff = 0;
            g_count = 0;
        }
        __syncthreads();
        if (tid == sh.s_seg) {
            unsigned cum = sh.s_cumafter;
            int cb = tid * 16;
            for (int k = 15; k >= 0; --k) {
                cum += loc[k];
                if (cum >= TOPK) { cb = tid * 16 + k; break; }
            }
            g_cutoff = cb;
        }
    }
    grid_bar(&sh);

    // ---- Stage 3: gather (recompute conf) + hist reset --------------------
    {
        int cut = g_cutoff;
        for (int k = 0; k < 9; k++) {
            int t = gid + k * NTHR;
            if (t >= NTOT) break;
            int HW, t2, off;
            float conf = conf_at(t, in13, in26, in52, HW, t2, off);
            if (!(conf > 0.5f)) continue;
            unsigned bits = __float_as_uint(conf);
            unsigned bin  = (bits - 0x3F000000u) >> 11;
            if (bin > NBINS - 1) bin = NBINS - 1;
            if ((int)bin < cut) continue;
            int b = t2 / (3 * HW);
            int r = t2 - b * 3 * HW;
            int a = r / HW;
            int p = r - a * HW;
            unsigned g = (unsigned)(off + (b * HW + p) * 3 + a);
            unsigned pos = atomicAdd(&g_count, 1u);
            if (pos < CAP)
                g_keys[pos] = ((unsigned long long)bits << 32) | (0xFFFFFFFFu - g);
        }
        if (gid < NBINS) g_hist[gid] = 0u;   // clean for next replay
    }
    grid_bar(&sh);

    // ---- Stage 4: bitonic sort (block 0) ----------------------------------
    if (blockIdx.x == 0) {
        if (tid == 0) {
            int M = (int)g_count; if (M > CAP) M = CAP;
            int n = TOPK; while (n < M) n <<= 1;
            sh.sM = M; sh.sn = n;
            g_Mv = (M < TOPK) ? M : TOPK;
        }
        __syncthreads();
        int M = sh.sM, n = sh.sn;
        for (int k = tid; k < n; k += BLK)
            sh.u.sk[k] = (k < M) ? g_keys[k] : 0ull;
        for (int ksz = 2; ksz <= n; ksz <<= 1)
            for (int j = ksz >> 1; j > 0; j >>= 1) {
                __syncthreads();
                for (int i = tid; i < n; i += BLK) {
                    int l = i ^ j;
                    if (l > i) {
                        unsigned long long A = sh.u.sk[i], B = sh.u.sk[l];
                        bool dec = ((i & ksz) == 0);
                        if (dec ? (A < B) : (A > B)) { sh.u.sk[i] = B; sh.u.sk[l] = A; }
                    }
                }
            }
        __syncthreads();
        for (int k = tid; k < TOPK; k += BLK) g_skeys[k] = sh.u.sk[k];
    }
    grid_bar(&sh);

    // ---- Stage 5: decode, one warp per candidate --------------------------
    {
        int r    = blockIdx.x * (BLK >> 5) + (tid >> 5);
        int lane = tid & 31;
        if (r < TOPK) {
            int M = g_Mv;
            if (r >= M) {
                if (lane < 7) g_cand[r * 7 + lane] = 0.f;
            } else {
                unsigned long long key = g_skeys[r];
                float conf = __uint_as_float((unsigned)(key >> 32));
                unsigned g = 0xFFFFFFFFu - (unsigned)(key & 0xFFFFFFFFu);
                const float* in; int HW, W, sc;
                if (g < N13)        { in = in13; HW = 169;  W = 13; sc = 0; }
                else if (g < OFF52) { in = in26; HW = 676;  W = 26; sc = 1; g -= OFF26; }
                else                { in = in52; HW = 2704; W = 52; sc = 2; g -= OFF52; }
                int a  = g % 3;
                int p  = g / 3;
                int b  = p / HW;
                int pp = p - b * HW;
                int x  = pp % W;
                int y  = pp / W;
                const float* base = in + (b * 255 + a * 85) * HW + pp;
                float chv = (lane < 4) ? base[lane * HW] : 0.f;
                float bv = -3.4e38f; int bi = 127;
#pragma unroll
                for (int k = 0; k < 3; k++) {
                    int c = lane + 32 * k;
                    if (c < 80) {
                        float v = base[(5 + c) * HW];
                        if (v > bv) { bv = v; bi = c; }
                    }
                }
#pragma unroll
                for (int off = 16; off; off >>= 1) {
                    float ov = __shfl_xor_sync(0xFFFFFFFFu, bv, off);
                    int   oi = __shfl_xor_sync(0xFFFFFFFFu, bi, off);
                    if (ov > bv || (ov == bv && oi < bi)) { bv = ov; bi = oi; }
                }
                float t0 = __shfl_sync(0xFFFFFFFFu, chv, 0);
                float t1 = __shfl_sync(0xFFFFFFFFu, chv, 1);
                float t2 = __shfl_sync(0xFFFFFFFFu, chv, 2);
                float t3 = __shfl_sync(0xFFFFFFFFu, chv, 3);
                if (lane == 0) {
                    float tx = sigm(t0);
                    float ty = sigm(t1);
                    float st = c_stride[sc];
                    float cx = ((float)x + tx) * st;
                    float cy = ((float)y + ty) * st;
                    float w  = c_anchors[sc][a][0] * expf(t2);
                    float h  = c_anchors[sc][a][1] * expf(t3);
                    float w0 = w * 0.5f, h0 = h * 0.5f;
                    float* o = &g_cand[r * 7];
                    o[0] = conf;
                    o[1] = cx - w0;
                    o[2] = cy - h0;
                    o[3] = cx + w0;
                    o[4] = cy + h0;
                    o[5] = (float)bi;
                    o[6] = (float)b;
                }
            }
        }
    }
    grid_bar(&sh);

    // ---- Stage 6: IoU bit-matrix ------------------------------------------
    {
        int j0 = tid, j1 = tid + BLK;
        float ax1 = g_cand[j0*7+1], ay1 = g_cand[j0*7+2];
        float ax2 = g_cand[j0*7+3], ay2 = g_cand[j0*7+4];
        float areaA = fmaxf(ax2-ax1, 0.f) * fmaxf(ay2-ay1, 0.f);
        float bx1 = g_cand[j1*7+1], by1 = g_cand[j1*7+2];
        float bx2 = g_cand[j1*7+3], by2 = g_cand[j1*7+4];
        float areaB = fmaxf(bx2-bx1, 0.f) * fmaxf(by2-by1, 0.f);
        int wid = tid >> 5, lane = tid & 31;
        for (int i = blockIdx.x; i < TOPK; i += GRID) {
            float ix1 = g_cand[i*7+1], iy1 = g_cand[i*7+2];
            float ix2 = g_cand[i*7+3], iy2 = g_cand[i*7+4];
            float areaI = fmaxf(ix2-ix1, 0.f) * fmaxf(iy2-iy1, 0.f);
            float xx1 = fmaxf(ix1, ax1), yy1 = fmaxf(iy1, ay1);
            float xx2 = fminf(ix2, ax2), yy2 = fminf(iy2, ay2);
            float inter = fmaxf(xx2-xx1, 0.f) * fmaxf(yy2-yy1, 0.f);
            float iouA = inter / (areaI + areaA - inter + 1e-9f);
            unsigned balA = __ballot_sync(0xFFFFFFFFu, (iouA > 0.3f) && (j0 > i));
            xx1 = fmaxf(ix1, bx1); yy1 = fmaxf(iy1, by1);
            xx2 = fminf(ix2, bx2); yy2 = fminf(iy2, by2);
            inter = fmaxf(xx2-xx1, 0.f) * fmaxf(yy2-yy1, 0.f);
            float iouB = inter / (areaI + areaB - inter + 1e-9f);
            unsigned balB = __ballot_sync(0xFFFFFFFFu, (iouB > 0.3f) && (j1 > i));
            if (lane == 0) {
                g_mask[i * 16 + wid]     = balA;
                g_mask[i * 16 + wid + 8] = balB;
            }
        }
    }
    grid_bar(&sh);

    // ---- Stage 7: serial greedy NMS + output (block 0) --------------------
    if (blockIdx.x == 0) {
        for (int idx = tid; idx < TOPK * 16; idx += BLK)
            sh.u.mask[idx] = g_mask[idx];
        if (tid < 16) {
            int M = g_Mv;
            int lo = tid * 32;
            unsigned w;
            if (M >= lo + 32)      w = 0xFFFFFFFFu;
            else if (M <= lo)      w = 0u;
            else                   w = (1u << (M - lo)) - 1u;
            sh.keep[tid] = w;
        }
        __syncthreads();
        if (tid == 0) {
            unsigned kw[16];
#pragma unroll
            for (int k = 0; k < 16; k++) kw[k] = sh.keep[k];
            for (int w = 0; w < 16; w++) {
                unsigned bits = kw[w];
                while (bits) {
                    int b = __ffs(bits) - 1;
                    const unsigned* mrow = &sh.u.mask[(w * 32 + b) * 16];
                    for (int u = w; u < 16; u++) kw[u] &= ~mrow[u];
                    bits = kw[w] & (0xFFFFFFFEu << b);
                }
            }
#pragma unroll
            for (int k = 0; k < 16; k++) sh.keep[k] = kw[k];
        }
        __syncthreads();
        for (int idx = tid; idx < TOPK * 7; idx += BLK) {
            int r = idx / 7;
            float kf = ((sh.keep[r >> 5] >> (r & 31)) & 1u) ? 1.0f : 0.0f;
            out[idx] = g_cand[idx] * kf;
        }
    }
}

// ---------------------------------------------------------------------------
extern "C" void kernel_launch(void* const* d_in, const int* in_sizes, int n_in,
                              void* d_out, int out_size) {
    const float* in13 = (const float*)d_in[0];
    const float* in26 = (const float*)d_in[1];
    const float* in52 = (const float*)d_in[2];
    float* out = (float*)d_out;
    detector_fused<<<GRID, BLK>>>(in13, in26, in52, out);
}